// round 15
// baseline (speedup 1.0000x reference)
#include <cuda_runtime.h>
#include <cuda_bf16.h>
#include <cuda_fp16.h>
#include <cstdint>

#define NUM_ITER 10
#define MU_      (1.0f/256.0f)
#define EPS_     1e-8f
#define CEXP     (-28.853900817779268f)   /* -(1/tau)*log2(e) */
#define CLOG     (-0.034657359027997264f) /* -tau*ln(2) */

#define BSTR      272
#define K8STR     272
#define B_OFF     0             /* bf16 B; becomes fp8 K after phase 2 */
#define S2_OFF    69632
#define T2_OFF    70656
#define U_OFF     71680
#define V_OFF     72704
#define RED_OFF   73728
#define UH_OFF    74752         /* u f16, 512B */
#define V8_OFF    75264         /* v fp8, 256B */
#define SMEM_TOTAL 75776

__device__ __forceinline__ uint32_t smem_u32(const void* p) {
    uint32_t a;
    asm("{ .reg .u64 t; cvta.to.shared.u64 t, %1; cvt.u32.u64 %0, t; }" : "=r"(a) : "l"(p));
    return a;
}
__device__ __forceinline__ float fsqrt_ap(float x) { float r; asm("sqrt.approx.f32 %0, %1;" : "=f"(r) : "f"(x)); return r; }
__device__ __forceinline__ float fex2_ap (float x) { float r; asm("ex2.approx.f32 %0, %1;"  : "=f"(r) : "f"(x)); return r; }
__device__ __forceinline__ float flg2_ap (float x) { float r; asm("lg2.approx.f32 %0, %1;"  : "=f"(r) : "f"(x)); return r; }
__device__ __forceinline__ float frcp_ap (float x) { float r; asm("rcp.approx.f32 %0, %1;"  : "=f"(r) : "f"(x)); return r; }
__device__ __forceinline__ uint32_t b2u(__nv_bfloat162 h) { return *reinterpret_cast<uint32_t*>(&h); }
__device__ __forceinline__ uint32_t pack_bf(float a, float b) { return b2u(__floats2bfloat162_rn(a, b)); }
__device__ __forceinline__ unsigned short pack_e4m3(float lo, float hi) {
    unsigned short p;
    asm("cvt.rn.satfinite.e4m3x2.f32 %0, %1, %2;" : "=h"(p) : "f"(hi), "f"(lo));
    return p;
}
/* 2 fp8 bytes (low half of x) -> f16x2, exact */
__device__ __forceinline__ uint32_t cvt8(uint32_t x) {
    uint32_t d;
    asm("cvt.rn.f16x2.e4m3x2 %0, %1;" : "=r"(d) : "h"((unsigned short)x));
    return d;
}
__device__ __forceinline__ float2 h2f2(uint32_t h2) {
    return __half22float2(*reinterpret_cast<__half2*>(&h2));
}
__device__ __forceinline__ uint32_t prmt3120(uint32_t a) {
    uint32_t d; asm("prmt.b32 %0, %1, %1, 0x3120;" : "=r"(d) : "r"(a)); return d;
}

__device__ __forceinline__ void mma16816(float* c, const uint32_t* a, uint32_t b0, uint32_t b1) {
    asm volatile(
        "mma.sync.aligned.m16n8k16.row.col.f32.bf16.bf16.f32 "
        "{%0,%1,%2,%3}, {%4,%5,%6,%7}, {%8,%9}, {%0,%1,%2,%3};"
        : "+f"(c[0]), "+f"(c[1]), "+f"(c[2]), "+f"(c[3])
        : "r"(a[0]), "r"(a[1]), "r"(a[2]), "r"(a[3]), "r"(b0), "r"(b1));
}
__device__ __forceinline__ void mma_h(float* c, const uint32_t* a, uint32_t b0, uint32_t b1) {
    asm volatile(
        "mma.sync.aligned.m16n8k16.row.col.f32.f16.f16.f32 "
        "{%0,%1,%2,%3}, {%4,%5,%6,%7}, {%8,%9}, {%0,%1,%2,%3};"
        : "+f"(c[0]), "+f"(c[1]), "+f"(c[2]), "+f"(c[3])
        : "r"(a[0]), "r"(a[1]), "r"(a[2]), "r"(a[3]), "r"(b0), "r"(b1));
}
__device__ __forceinline__ void mma_fp8(float* c, const uint32_t* a, uint32_t b0, uint32_t b1) {
    asm volatile(
        "mma.sync.aligned.m16n8k32.row.col.f32.e4m3.e4m3.f32 "
        "{%0,%1,%2,%3}, {%4,%5,%6,%7}, {%8,%9}, {%0,%1,%2,%3};"
        : "+f"(c[0]), "+f"(c[1]), "+f"(c[2]), "+f"(c[3])
        : "r"(a[0]), "r"(a[1]), "r"(a[2]), "r"(a[3]), "r"(b0), "r"(b1));
}
__device__ __forceinline__ void ldsm4(uint32_t* r, uint32_t addr) {
    asm volatile("ldmatrix.sync.aligned.m8n8.x4.shared.b16 {%0,%1,%2,%3}, [%4];"
        : "=r"(r[0]), "=r"(r[1]), "=r"(r[2]), "=r"(r[3]) : "r"(addr));
}
__device__ __forceinline__ void ldsm4t(uint32_t* r, uint32_t addr) {
    asm volatile("ldmatrix.sync.aligned.m8n8.x4.trans.shared.b16 {%0,%1,%2,%3}, [%4];"
        : "=r"(r[0]), "=r"(r[1]), "=r"(r[2]), "=r"(r[3]) : "r"(addr));
}

__device__ float g_partial[1024];
__device__ int   g_count = 0;

__global__ void __launch_bounds__(512, 1)
sinkhorn_kernel(const float* __restrict__ src, const float* __restrict__ tgt,
                float* __restrict__ out) {
    extern __shared__ char sm[];
    const int tid = threadIdx.x, wid = tid >> 5, lane = tid & 31;
    const int g = lane >> 2, t = lane & 3;
    const int bt = blockIdx.x;

    float* s2arr = (float*)(sm + S2_OFF);
    float* t2arr = (float*)(sm + T2_OFF);
    float* uarr  = (float*)(sm + U_OFF);
    float* varr  = (float*)(sm + V_OFF);
    float* red   = (float*)(sm + RED_OFF);
    __half* uh   = (__half*)(sm + UH_OFF);
    char* v8c = sm + V8_OFF;

    /* ---- phase 1a: tgt -> smem bf16 [n][k]; t2 row sums ---- */
    {
        const float4* t4 = reinterpret_cast<const float4*>(tgt) + (size_t)bt * 8192;
        #pragma unroll 4
        for (int j = 0; j < 16; j++) {
            int row = 16 * j + wid;
            float4 f = t4[row * 32 + lane];
            float ss = f.x*f.x + f.y*f.y + f.z*f.z + f.w*f.w;
            #pragma unroll
            for (int o = 16; o > 0; o >>= 1) ss += __shfl_xor_sync(0xffffffffu, ss, o);
            if (lane == 0) t2arr[row] = ss;
            *reinterpret_cast<uint2*>(sm + B_OFF + row * BSTR + lane * 8) =
                make_uint2(pack_bf(f.x, f.y), pack_bf(f.z, f.w));
        }
    }

    /* ---- phase 1b: src -> A fragments (16-row strip/warp); s2 row sums ---- */
    uint32_t afrag[8][4];
    {
        const float2* a2 = reinterpret_cast<const float2*>(src) + (size_t)bt * 16384;
        const int r0 = 16 * wid + g, r1 = r0 + 8;
        float s0 = 0.0f, s1 = 0.0f;
        #pragma unroll
        for (int ks = 0; ks < 8; ks++) {
            int kk = 8 * ks + t;
            float2 f00 = a2[r0 * 64 + kk];
            float2 f10 = a2[r1 * 64 + kk];
            float2 f01 = a2[r0 * 64 + kk + 4];
            float2 f11 = a2[r1 * 64 + kk + 4];
            afrag[ks][0] = pack_bf(f00.x, f00.y);
            afrag[ks][1] = pack_bf(f10.x, f10.y);
            afrag[ks][2] = pack_bf(f01.x, f01.y);
            afrag[ks][3] = pack_bf(f11.x, f11.y);
            s0 += f00.x*f00.x + f00.y*f00.y + f01.x*f01.x + f01.y*f01.y;
            s1 += f10.x*f10.x + f10.y*f10.y + f11.x*f11.x + f11.y*f11.y;
        }
        s0 += __shfl_xor_sync(0xffffffffu, s0, 1); s0 += __shfl_xor_sync(0xffffffffu, s0, 2);
        s1 += __shfl_xor_sync(0xffffffffu, s1, 1); s1 += __shfl_xor_sync(0xffffffffu, s1, 2);
        if (t == 0) { s2arr[r0] = s0; s2arr[r1] = s1; }
    }
    if (tid < 256) v8c[tid] = (char)0x38;     /* e4m3(1.0) */
    __syncthreads();

    /* ---- phase 2: HMMA GEMM fused with cost -> K fp8 held in regs ---- */
    uint32_t k8regs[32];
    {
        const int r0 = 16 * wid + g, r1 = r0 + 8;
        const float s20 = s2arr[r0], s21 = s2arr[r1];
        #pragma unroll 2
        for (int nt = 0; nt < 32; nt++) {
            const char* bp = sm + B_OFF + (nt * 8 + g) * BSTR + 4 * t;
            float acc[4] = {0.f, 0.f, 0.f, 0.f};
            #pragma unroll
            for (int ks = 0; ks < 8; ks++) {
                uint32_t b0 = *reinterpret_cast<const uint32_t*>(bp + 32 * ks);
                uint32_t b1 = *reinterpret_cast<const uint32_t*>(bp + 32 * ks + 16);
                mma16816(acc, afrag[ks], b0, b1);
            }
            int c0 = nt * 8 + 2 * t;
            float t20 = t2arr[c0], t21 = t2arr[c0 + 1];
            float x;
            x = fmaxf(s20 + t20 - 2.0f * acc[0], 0.0f); float k00 = fex2_ap(fsqrt_ap(x) * CEXP);
            x = fmaxf(s20 + t21 - 2.0f * acc[1], 0.0f); float k01 = fex2_ap(fsqrt_ap(x) * CEXP);
            x = fmaxf(s21 + t20 - 2.0f * acc[2], 0.0f); float k10 = fex2_ap(fsqrt_ap(x) * CEXP);
            x = fmaxf(s21 + t21 - 2.0f * acc[3], 0.0f); float k11 = fex2_ap(fsqrt_ap(x) * CEXP);
            k8regs[nt] = (uint32_t)pack_e4m3(k00, k01) | ((uint32_t)pack_e4m3(k10, k11) << 16);
        }
    }
    __syncthreads();     /* all B reads done -> safe to overwrite with fp8 K */

    /* ---- phase 2b: dump fp8 K row-major over B region ---- */
    {
        const int r0 = 16 * wid + g, r1 = r0 + 8;
        char* k8 = sm + B_OFF;
        #pragma unroll
        for (int nt = 0; nt < 32; nt++) {
            int c0 = nt * 8 + 2 * t;
            *reinterpret_cast<unsigned short*>(k8 + r0 * K8STR + c0) =
                (unsigned short)(k8regs[nt] & 0xffff);
            *reinterpret_cast<unsigned short*>(k8 + r1 * K8STR + c0) =
                (unsigned short)(k8regs[nt] >> 16);
        }
    }
    __syncthreads();

    /* ---- phase 3 prologue: hoist ALL K fragments into registers ----
       ua_f[s]: raw fp8 A-frags of K rows [16w,16w+16), k=32s..32s+31
                (lane (g,t): a0=K[16w+g][32s+4t..+3], a1=row+8, a2=+16 cols, a3=both)
       va_p[..]: prmt'd fp8 trans-fragments of K^T (R10/R12 mapping)      */
    uint32_t ua_f[8][4];
    uint32_t va_p[32];
    {
        const int l7 = lane & 7, q = lane >> 3;
        const uint32_t k8b = smem_u32(sm + B_OFF);
        const uint32_t ua8 = k8b + (16 * wid + l7 + (q & 1) * 8) * K8STR + (q >> 1) * 16;
        const uint32_t va8 = k8b + lane * K8STR + 16 * wid;
        #pragma unroll
        for (int s = 0; s < 8; s++) ldsm4(ua_f[s], ua8 + 32 * s);
        #pragma unroll
        for (int s = 0; s < 16; s += 2) {
            uint32_t x[4];
            ldsm4t(x, va8 + s * (16 * K8STR));
            va_p[2 * s + 0] = prmt3120(x[0]);
            va_p[2 * s + 1] = prmt3120(x[1]);
            va_p[2 * s + 2] = prmt3120(x[2]);
            va_p[2 * s + 3] = prmt3120(x[3]);
        }
    }

    /* ---- phase 3: 10 Sinkhorn iterations, zero K smem traffic ---- */
    {
        const uint32_t* v8w = (const uint32_t*)(sm + V8_OFF);
        const uint32_t* uhw = (const uint32_t*)(sm + UH_OFF);

        for (int it = 0; it < NUM_ITER; it++) {
            /* u = mu / (K v + eps): fp8 mma from register fragments */
            float acc[4] = {0.f, 0.f, 0.f, 0.f};
            #pragma unroll
            for (int s = 0; s < 8; s++)
                mma_fp8(acc, ua_f[s], v8w[8 * s + t], v8w[8 * s + 4 + t]);
            if (t == 0) {
                int r = 16 * wid + g;
                float u0 = MU_ * frcp_ap(acc[0] + EPS_);
                float u1 = MU_ * frcp_ap(acc[2] + EPS_);
                uarr[r] = u0; uarr[r + 8] = u1;
                uh[r] = __float2half(u0); uh[r + 8] = __float2half(u1);
            }
            __syncthreads();
            /* v = mu / (K^T u + eps): cvt register fragments -> f16 mma.
               Row permutation: acc row g -> m=16w+2g, row g+8 -> m=16w+2g+1 */
            float cA[4] = {0.f, 0.f, 0.f, 0.f}, cB[4] = {0.f, 0.f, 0.f, 0.f};
            #pragma unroll
            for (int s8 = 0; s8 < 8; s8++) {
                uint32_t p0 = va_p[4 * s8], p1 = va_p[4 * s8 + 1];
                uint32_t a0[4] = { cvt8(p0), cvt8(p0 >> 16), cvt8(p1), cvt8(p1 >> 16) };
                mma_h(cA, a0, uhw[16 * s8 + t], uhw[16 * s8 + 4 + t]);
                uint32_t p2 = va_p[4 * s8 + 2], p3 = va_p[4 * s8 + 3];
                uint32_t a1[4] = { cvt8(p2), cvt8(p2 >> 16), cvt8(p3), cvt8(p3 >> 16) };
                mma_h(cB, a1, uhw[16 * s8 + 8 + t], uhw[16 * s8 + 12 + t]);
            }
            if (t == 0) {
                int m0 = 16 * wid + 2 * g, m1 = m0 + 1;
                float v0 = MU_ * frcp_ap(cA[0] + cB[0] + EPS_);
                float v1 = MU_ * frcp_ap(cA[2] + cB[2] + EPS_);
                varr[m0] = v0; varr[m1] = v1;
                v8c[m0] = (char)(pack_e4m3(v0, 0.f) & 0xff);
                v8c[m1] = (char)(pack_e4m3(v1, 0.f) & 0xff);
            }
            __syncthreads();
        }
    }

    /* ---- phase 4: loss from register fragments.
       lane (g,t) of warp w holds rows r0=16w+g, r1=r0+8;
       per s: cols 32s+4t..+3 (a0/a1) and 32s+16+4t..+3 (a2/a3). ---- */
    {
        const int r0 = 16 * wid + g, r1 = r0 + 8;
        float ar0 = 0.0f, ar1 = 0.0f;
        #pragma unroll
        for (int s = 0; s < 8; s++) {
            int c0 = 32 * s + 4 * t;
            float4 v0 = *reinterpret_cast<const float4*>(varr + c0);
            float4 v1 = *reinterpret_cast<const float4*>(varr + c0 + 16);
            float2 f0, f1;
            f0 = h2f2(cvt8(ua_f[s][0])); f1 = h2f2(cvt8(ua_f[s][0] >> 16));
            ar0 += f0.x * v0.x * flg2_ap(f0.x) + f0.y * v0.y * flg2_ap(f0.y)
                 + f1.x * v0.z * flg2_ap(f1.x) + f1.y * v0.w * flg2_ap(f1.y);
            f0 = h2f2(cvt8(ua_f[s][2])); f1 = h2f2(cvt8(ua_f[s][2] >> 16));
            ar0 += f0.x * v1.x * flg2_ap(f0.x) + f0.y * v1.y * flg2_ap(f0.y)
                 + f1.x * v1.z * flg2_ap(f1.x) + f1.y * v1.w * flg2_ap(f1.y);
            f0 = h2f2(cvt8(ua_f[s][1])); f1 = h2f2(cvt8(ua_f[s][1] >> 16));
            ar1 += f0.x * v0.x * flg2_ap(f0.x) + f0.y * v0.y * flg2_ap(f0.y)
                 + f1.x * v0.z * flg2_ap(f1.x) + f1.y * v0.w * flg2_ap(f1.y);
            f0 = h2f2(cvt8(ua_f[s][3])); f1 = h2f2(cvt8(ua_f[s][3] >> 16));
            ar1 += f0.x * v1.x * flg2_ap(f0.x) + f0.y * v1.y * flg2_ap(f0.y)
                 + f1.x * v1.z * flg2_ap(f1.x) + f1.y * v1.w * flg2_ap(f1.y);
        }
        float acc = (ar0 * uarr[r0] + ar1 * uarr[r1]) * CLOG;
        #pragma unroll
        for (int o = 16; o > 0; o >>= 1) acc += __shfl_xor_sync(0xffffffffu, acc, o);
        if (lane == 0) red[wid] = acc;
        __syncthreads();
        if (tid == 0) {
            float tsum = 0.0f;
            #pragma unroll
            for (int w = 0; w < 16; w++) tsum += red[w];
            g_partial[bt] = tsum;
        }
    }

    /* ---- phase 5: last block reduces g_partial -> out ---- */
    __shared__ int is_last;
    if (tid == 0) {
        __threadfence();
        int c = atomicAdd(&g_count, 1);
        is_last = (c == 1023);
    }
    __syncthreads();
    if (is_last) {
        if (tid == 0) g_count = 0;
        float s = g_partial[tid] + g_partial[tid + 512];
        #pragma unroll
        for (int o = 16; o > 0; o >>= 1) s += __shfl_xor_sync(0xffffffffu, s, o);
        if (lane == 0) red[wid] = s;
        __syncthreads();
        if (tid == 0) {
            float tsum = 0.0f;
            #pragma unroll
            for (int w = 0; w < 16; w++) tsum += red[w];
            out[0] = tsum * (1.0f / 1024.0f);
        }
    }
}

extern "C" void kernel_launch(void* const* d_in, const int* in_sizes, int n_in,
                              void* d_out, int out_size) {
    const float* src = (const float*)d_in[0];
    const float* tgt = (const float*)d_in[1];
    float* out = (float*)d_out;
    cudaFuncSetAttribute(sinkhorn_kernel, cudaFuncAttributeMaxDynamicSharedMemorySize, SMEM_TOTAL);
    sinkhorn_kernel<<<1024, 512, SMEM_TOTAL>>>(src, tgt, out);
}

// round 17
// speedup vs baseline: 1.9126x; 1.9126x over previous
#include <cuda_runtime.h>
#include <cuda_bf16.h>
#include <cuda_fp16.h>
#include <cstdint>

#define NUM_ITER 10
#define MU_      (1.0f/256.0f)
#define EPS_     1e-8f
#define CEXP     (-28.853900817779268f)   /* -(1/tau)*log2(e) */
#define CLOG     (-0.034657359027997264f) /* -tau*ln(2) */

#define BSTR      272
#define K8STR     272
#define B_OFF     0             /* bf16 B; becomes fp8 K after phase 2 */
#define S2_OFF    69632
#define T2_OFF    70656
#define U_OFF     71680
#define V_OFF     72704
#define RED_OFF   73728
#define UH_OFF    74752         /* u f16, 512B */
#define V8_OFF    75264         /* v fp8, 256B */
#define SMEM_TOTAL 75776

__device__ __forceinline__ uint32_t smem_u32(const void* p) {
    uint32_t a;
    asm("{ .reg .u64 t; cvta.to.shared.u64 t, %1; cvt.u32.u64 %0, t; }" : "=r"(a) : "l"(p));
    return a;
}
__device__ __forceinline__ float fsqrt_ap(float x) { float r; asm("sqrt.approx.f32 %0, %1;" : "=f"(r) : "f"(x)); return r; }
__device__ __forceinline__ float fex2_ap (float x) { float r; asm("ex2.approx.f32 %0, %1;"  : "=f"(r) : "f"(x)); return r; }
__device__ __forceinline__ float flg2_ap (float x) { float r; asm("lg2.approx.f32 %0, %1;"  : "=f"(r) : "f"(x)); return r; }
__device__ __forceinline__ float frcp_ap (float x) { float r; asm("rcp.approx.f32 %0, %1;"  : "=f"(r) : "f"(x)); return r; }
__device__ __forceinline__ uint32_t b2u(__nv_bfloat162 h) { return *reinterpret_cast<uint32_t*>(&h); }
__device__ __forceinline__ uint32_t pack_bf(float a, float b) { return b2u(__floats2bfloat162_rn(a, b)); }
__device__ __forceinline__ unsigned short pack_e4m3(float lo, float hi) {
    unsigned short p;
    asm("cvt.rn.satfinite.e4m3x2.f32 %0, %1, %2;" : "=h"(p) : "f"(hi), "f"(lo));
    return p;
}
/* 2 fp8 bytes (low half of x) -> f16x2, exact */
__device__ __forceinline__ uint32_t cvt8(uint32_t x) {
    uint32_t d;
    asm("cvt.rn.f16x2.e4m3x2 %0, %1;" : "=r"(d) : "h"((unsigned short)x));
    return d;
}
__device__ __forceinline__ float2 h2f2(uint32_t h2) {
    return __half22float2(*reinterpret_cast<__half2*>(&h2));
}
__device__ __forceinline__ uint32_t prmt3120(uint32_t a) {
    uint32_t d; asm("prmt.b32 %0, %1, %1, 0x3120;" : "=r"(d) : "r"(a)); return d;
}

__device__ __forceinline__ void mma16816(float* c, const uint32_t* a, uint32_t b0, uint32_t b1) {
    asm volatile(
        "mma.sync.aligned.m16n8k16.row.col.f32.bf16.bf16.f32 "
        "{%0,%1,%2,%3}, {%4,%5,%6,%7}, {%8,%9}, {%0,%1,%2,%3};"
        : "+f"(c[0]), "+f"(c[1]), "+f"(c[2]), "+f"(c[3])
        : "r"(a[0]), "r"(a[1]), "r"(a[2]), "r"(a[3]), "r"(b0), "r"(b1));
}
__device__ __forceinline__ void mma_h(float* c, const uint32_t* a, uint32_t b0, uint32_t b1) {
    asm volatile(
        "mma.sync.aligned.m16n8k16.row.col.f32.f16.f16.f32 "
        "{%0,%1,%2,%3}, {%4,%5,%6,%7}, {%8,%9}, {%0,%1,%2,%3};"
        : "+f"(c[0]), "+f"(c[1]), "+f"(c[2]), "+f"(c[3])
        : "r"(a[0]), "r"(a[1]), "r"(a[2]), "r"(a[3]), "r"(b0), "r"(b1));
}
__device__ __forceinline__ void mma_fp8(float* c, const uint32_t* a, uint32_t b0, uint32_t b1) {
    asm volatile(
        "mma.sync.aligned.m16n8k32.row.col.f32.e4m3.e4m3.f32 "
        "{%0,%1,%2,%3}, {%4,%5,%6,%7}, {%8,%9}, {%0,%1,%2,%3};"
        : "+f"(c[0]), "+f"(c[1]), "+f"(c[2]), "+f"(c[3])
        : "r"(a[0]), "r"(a[1]), "r"(a[2]), "r"(a[3]), "r"(b0), "r"(b1));
}
__device__ __forceinline__ void ldsm4(uint32_t* r, uint32_t addr) {
    asm volatile("ldmatrix.sync.aligned.m8n8.x4.shared.b16 {%0,%1,%2,%3}, [%4];"
        : "=r"(r[0]), "=r"(r[1]), "=r"(r[2]), "=r"(r[3]) : "r"(addr));
}
__device__ __forceinline__ void ldsm4t(uint32_t* r, uint32_t addr) {
    asm volatile("ldmatrix.sync.aligned.m8n8.x4.trans.shared.b16 {%0,%1,%2,%3}, [%4];"
        : "=r"(r[0]), "=r"(r[1]), "=r"(r[2]), "=r"(r[3]) : "r"(addr));
}

__device__ float g_partial[1024];
__device__ int   g_count = 0;

__global__ void __launch_bounds__(512, 1)
sinkhorn_kernel(const float* __restrict__ src, const float* __restrict__ tgt,
                float* __restrict__ out) {
    extern __shared__ char sm[];
    const int tid = threadIdx.x, wid = tid >> 5, lane = tid & 31;
    const int g = lane >> 2, t = lane & 3;
    const int bt = blockIdx.x;

    float* s2arr = (float*)(sm + S2_OFF);
    float* t2arr = (float*)(sm + T2_OFF);
    float* uarr  = (float*)(sm + U_OFF);
    float* varr  = (float*)(sm + V_OFF);
    float* red   = (float*)(sm + RED_OFF);
    __half* uh   = (__half*)(sm + UH_OFF);
    char* v8c = sm + V8_OFF;

    /* ---- phase 1a: tgt -> smem bf16 [n][k]; t2 row sums ---- */
    {
        const float4* t4 = reinterpret_cast<const float4*>(tgt) + (size_t)bt * 8192;
        #pragma unroll 4
        for (int j = 0; j < 16; j++) {
            int row = 16 * j + wid;
            float4 f = t4[row * 32 + lane];
            float ss = f.x*f.x + f.y*f.y + f.z*f.z + f.w*f.w;
            #pragma unroll
            for (int o = 16; o > 0; o >>= 1) ss += __shfl_xor_sync(0xffffffffu, ss, o);
            if (lane == 0) t2arr[row] = ss;
            *reinterpret_cast<uint2*>(sm + B_OFF + row * BSTR + lane * 8) =
                make_uint2(pack_bf(f.x, f.y), pack_bf(f.z, f.w));
        }
    }

    /* ---- phase 1b: src -> A fragments (16-row strip/warp); s2 row sums ---- */
    uint32_t afrag[8][4];
    {
        const float2* a2 = reinterpret_cast<const float2*>(src) + (size_t)bt * 16384;
        const int r0 = 16 * wid + g, r1 = r0 + 8;
        float s0 = 0.0f, s1 = 0.0f;
        #pragma unroll
        for (int ks = 0; ks < 8; ks++) {
            int kk = 8 * ks + t;
            float2 f00 = a2[r0 * 64 + kk];
            float2 f10 = a2[r1 * 64 + kk];
            float2 f01 = a2[r0 * 64 + kk + 4];
            float2 f11 = a2[r1 * 64 + kk + 4];
            afrag[ks][0] = pack_bf(f00.x, f00.y);
            afrag[ks][1] = pack_bf(f10.x, f10.y);
            afrag[ks][2] = pack_bf(f01.x, f01.y);
            afrag[ks][3] = pack_bf(f11.x, f11.y);
            s0 += f00.x*f00.x + f00.y*f00.y + f01.x*f01.x + f01.y*f01.y;
            s1 += f10.x*f10.x + f10.y*f10.y + f11.x*f11.x + f11.y*f11.y;
        }
        s0 += __shfl_xor_sync(0xffffffffu, s0, 1); s0 += __shfl_xor_sync(0xffffffffu, s0, 2);
        s1 += __shfl_xor_sync(0xffffffffu, s1, 1); s1 += __shfl_xor_sync(0xffffffffu, s1, 2);
        if (t == 0) { s2arr[r0] = s0; s2arr[r1] = s1; }
    }
    if (tid < 256) v8c[tid] = (char)0x38;     /* e4m3(1.0) */
    __syncthreads();

    /* ---- phase 2: HMMA GEMM fused with cost -> K fp8 held in regs ---- */
    uint32_t k8regs[32];
    {
        const int r0 = 16 * wid + g, r1 = r0 + 8;
        const float s20 = s2arr[r0], s21 = s2arr[r1];
        #pragma unroll 2
        for (int nt = 0; nt < 32; nt++) {
            const char* bp = sm + B_OFF + (nt * 8 + g) * BSTR + 4 * t;
            float acc[4] = {0.f, 0.f, 0.f, 0.f};
            #pragma unroll
            for (int ks = 0; ks < 8; ks++) {
                uint32_t b0 = *reinterpret_cast<const uint32_t*>(bp + 32 * ks);
                uint32_t b1 = *reinterpret_cast<const uint32_t*>(bp + 32 * ks + 16);
                mma16816(acc, afrag[ks], b0, b1);
            }
            int c0 = nt * 8 + 2 * t;
            float t20 = t2arr[c0], t21 = t2arr[c0 + 1];
            float x;
            x = fmaxf(s20 + t20 - 2.0f * acc[0], 0.0f); float k00 = fex2_ap(fsqrt_ap(x) * CEXP);
            x = fmaxf(s20 + t21 - 2.0f * acc[1], 0.0f); float k01 = fex2_ap(fsqrt_ap(x) * CEXP);
            x = fmaxf(s21 + t20 - 2.0f * acc[2], 0.0f); float k10 = fex2_ap(fsqrt_ap(x) * CEXP);
            x = fmaxf(s21 + t21 - 2.0f * acc[3], 0.0f); float k11 = fex2_ap(fsqrt_ap(x) * CEXP);
            k8regs[nt] = (uint32_t)pack_e4m3(k00, k01) | ((uint32_t)pack_e4m3(k10, k11) << 16);
        }
    }
    __syncthreads();     /* all B reads done -> safe to overwrite with fp8 K */

    /* ---- phase 2b: dump fp8 K row-major over B region ---- */
    {
        const int r0 = 16 * wid + g, r1 = r0 + 8;
        char* k8 = sm + B_OFF;
        #pragma unroll
        for (int nt = 0; nt < 32; nt++) {
            int c0 = nt * 8 + 2 * t;
            *reinterpret_cast<unsigned short*>(k8 + r0 * K8STR + c0) =
                (unsigned short)(k8regs[nt] & 0xffff);
            *reinterpret_cast<unsigned short*>(k8 + r1 * K8STR + c0) =
                (unsigned short)(k8regs[nt] >> 16);
        }
    }
    __syncthreads();

    /* ---- phase 3 prologue: hoist ONLY the u-phase fragments (32 regs) ---- */
    uint32_t ua_f[8][4];
    {
        const int l7 = lane & 7, q = lane >> 3;
        const uint32_t k8b = smem_u32(sm + B_OFF);
        const uint32_t ua8 = k8b + (16 * wid + l7 + (q & 1) * 8) * K8STR + (q >> 1) * 16;
        #pragma unroll
        for (int s = 0; s < 8; s++) ldsm4(ua_f[s], ua8 + 32 * s);
    }

    /* ---- phase 3: 10 Sinkhorn iterations; u-phase register-fed, v-phase ldsm ---- */
    {
        const int l7 = lane & 7, q = lane >> 3;
        const uint32_t va8 = smem_u32(sm + B_OFF) + lane * K8STR + 16 * wid;
        const uint32_t* v8w = (const uint32_t*)(sm + V8_OFF);
        const uint32_t* uhw = (const uint32_t*)(sm + UH_OFF);
        (void)l7; (void)q;

        for (int it = 0; it < NUM_ITER; it++) {
            /* u = mu / (K v + eps): fp8 mma from register fragments */
            float acc[4] = {0.f, 0.f, 0.f, 0.f};
            #pragma unroll
            for (int s = 0; s < 8; s++)
                mma_fp8(acc, ua_f[s], v8w[8 * s + t], v8w[8 * s + 4 + t]);
            if (t == 0) {
                int r = 16 * wid + g;
                float u0 = MU_ * frcp_ap(acc[0] + EPS_);
                float u1 = MU_ * frcp_ap(acc[2] + EPS_);
                uarr[r] = u0; uarr[r + 8] = u1;
                uh[r] = __float2half(u0); uh[r + 8] = __float2half(u1);
            }
            __syncthreads();
            /* v = mu / (K^T u + eps): trans-ldsm fp8 + PRMT + cvt -> f16 mma.
               Row permutation: acc row g -> m=16w+2g, row g+8 -> m=16w+2g+1 */
            float cA[4] = {0.f, 0.f, 0.f, 0.f}, cB[4] = {0.f, 0.f, 0.f, 0.f};
            #pragma unroll
            for (int s = 0; s < 16; s += 2) {
                uint32_t x[4];
                ldsm4t(x, va8 + s * (16 * K8STR));
                uint32_t p0 = prmt3120(x[0]), p1 = prmt3120(x[1]);
                uint32_t a0[4] = { cvt8(p0), cvt8(p0 >> 16), cvt8(p1), cvt8(p1 >> 16) };
                mma_h(cA, a0, uhw[8 * s + t], uhw[8 * s + 4 + t]);
                uint32_t p2 = prmt3120(x[2]), p3 = prmt3120(x[3]);
                uint32_t a1[4] = { cvt8(p2), cvt8(p2 >> 16), cvt8(p3), cvt8(p3 >> 16) };
                mma_h(cB, a1, uhw[8 * (s + 1) + t], uhw[8 * (s + 1) + 4 + t]);
            }
            if (t == 0) {
                int m0 = 16 * wid + 2 * g, m1 = m0 + 1;
                float v0 = MU_ * frcp_ap(cA[0] + cB[0] + EPS_);
                float v1 = MU_ * frcp_ap(cA[2] + cB[2] + EPS_);
                varr[m0] = v0; varr[m1] = v1;
                v8c[m0] = (char)(pack_e4m3(v0, 0.f) & 0xff);
                v8c[m1] = (char)(pack_e4m3(v1, 0.f) & 0xff);
            }
            __syncthreads();
        }
    }

    /* ---- phase 4: loss = sum u K8 v c8, c8 = CLOG * log2(K8), from smem ---- */
    {
        const int row = tid >> 1, half = tid & 1;
        const uint4* kr4 = reinterpret_cast<const uint4*>(sm + B_OFF + row * K8STR + half * 128);
        const float* vv = varr + half * 128;
        float acc = 0.0f;
        #pragma unroll
        for (int j = 0; j < 8; j++) {
            uint4 q4 = kr4[j];
            uint32_t ws[4] = {q4.x, q4.y, q4.z, q4.w};
            #pragma unroll
            for (int i = 0; i < 4; i++) {
                float2 f0 = h2f2(cvt8(ws[i]));
                float2 f1 = h2f2(cvt8(ws[i] >> 16));
                int vb = 16 * j + 4 * i;
                acc += f0.x * vv[vb]     * flg2_ap(f0.x);
                acc += f0.y * vv[vb + 1] * flg2_ap(f0.y);
                acc += f1.x * vv[vb + 2] * flg2_ap(f1.x);
                acc += f1.y * vv[vb + 3] * flg2_ap(f1.y);
            }
        }
        acc *= uarr[row] * CLOG;
        #pragma unroll
        for (int o = 16; o > 0; o >>= 1) acc += __shfl_xor_sync(0xffffffffu, acc, o);
        if (lane == 0) red[wid] = acc;
        __syncthreads();
        if (tid == 0) {
            float tsum = 0.0f;
            #pragma unroll
            for (int w = 0; w < 16; w++) tsum += red[w];
            g_partial[bt] = tsum;
        }
    }

    /* ---- phase 5: last block reduces g_partial -> out ---- */
    __shared__ int is_last;
    if (tid == 0) {
        __threadfence();
        int c = atomicAdd(&g_count, 1);
        is_last = (c == 1023);
    }
    __syncthreads();
    if (is_last) {
        if (tid == 0) g_count = 0;
        float s = g_partial[tid] + g_partial[tid + 512];
        #pragma unroll
        for (int o = 16; o > 0; o >>= 1) s += __shfl_xor_sync(0xffffffffu, s, o);
        if (lane == 0) red[wid] = s;
        __syncthreads();
        if (tid == 0) {
            float tsum = 0.0f;
            #pragma unroll
            for (int w = 0; w < 16; w++) tsum += red[w];
            out[0] = tsum * (1.0f / 1024.0f);
        }
    }
}

extern "C" void kernel_launch(void* const* d_in, const int* in_sizes, int n_in,
                              void* d_out, int out_size) {
    const float* src = (const float*)d_in[0];
    const float* tgt = (const float*)d_in[1];
    float* out = (float*)d_out;
    cudaFuncSetAttribute(sinkhorn_kernel, cudaFuncAttributeMaxDynamicSharedMemorySize, SMEM_TOTAL);
    sinkhorn_kernel<<<1024, 512, SMEM_TOTAL>>>(src, tgt, out);
}